// round 13
// baseline (speedup 1.0000x reference)
#include <cuda_runtime.h>
#include <cuda_fp16.h>
#include <cstdint>

#define EMB      128
#define NRAD     16
#define N_ATOMS_ 100000
#define N_EDGES_ 1000000
#define N_ELEM   95
#define TILE     128
#define NTILES   ((N_EDGES_ + TILE - 1) / TILE)   // 7813
#define GRID_MAIN 296
#define THREADS  256

// ---------------- smem layout (bytes, dynamic) ----------------
#define OFF_BT2   0                    // W3^T fp16 frags [ks(8)][ntp(4x2)][q(8)][c(4)]x16B = 32KB
#define OFF_BT1   32768                // W_rbf^T fp16 frags = 4KB
#define OFF_RBFH  36864                // rbf tile fp16 A-frags, x2 buffers = 8KB
#define OFF_BIAS  45056                // b_rbf [128] f32
#define OFF_ZP    45568                // zp pair-index [128] int, x2 buffers = 1KB
#define OFF_SCR   46592                // per-warp transpose scratch: 8 x 16 x 272B
#define SCR_WARP  4352                 // 16 rows x 272B (64 floats + 4-word pad)
#define SMEM_DYN  (OFF_SCR + 8 * SCR_WARP)   // 81408

// prep1 fp32 projections; prep2 merged fp16 pair table (LINEAR n layout)
__device__ float g_EW1f[N_ELEM * EMB];
__device__ float g_EW2f[N_ELEM * EMB];
__device__ __align__(16) __half g_EWPh[N_ELEM * N_ELEM * EMB];   // 2.31MB

// ---------------- helpers ----------------
__device__ __forceinline__ float silu_tanh(float x) {
    float t;
    asm("tanh.approx.f32 %0, %1;" : "=f"(t) : "f"(0.5f * x));
    return 0.5f * x * (1.0f + t);
}
__device__ __forceinline__ uint32_t pack2(float lo, float hi) {
    uint32_t r;
    asm("cvt.rn.f16x2.f32 %0, %1, %2;" : "=r"(r) : "f"(hi), "f"(lo));
    return r;
}
__device__ __forceinline__ void mma_f16(float* d,
    uint32_t a0, uint32_t a1, uint32_t a2, uint32_t a3,
    uint32_t b0, uint32_t b1) {
    asm volatile(
        "mma.sync.aligned.m16n8k16.row.col.f32.f16.f16.f32 "
        "{%0,%1,%2,%3}, {%4,%5,%6,%7}, {%8,%9}, {%0,%1,%2,%3};"
        : "+f"(d[0]), "+f"(d[1]), "+f"(d[2]), "+f"(d[3])
        : "r"(a0), "r"(a1), "r"(a2), "r"(a3), "r"(b0), "r"(b1));
}
__device__ __forceinline__ int physmap(int kk) {
    return 4 * ((kk & 7) >> 1) + 2 * (kk >> 3) + (kk & 1);
}

// ---------------- prep1: EW1f = emb@W1 + b, EW2f = emb@W2 (fp32 linear) ----------------
__global__ void prep_kernel(const float* __restrict__ emb, const float* __restrict__ W,
                            const float* __restrict__ b) {
    __shared__ float p1[EMB], p2[EMB];
    int z = blockIdx.x, n = threadIdx.x & 127, h = threadIdx.x >> 7;
    const float* er = emb + z * EMB;
    float s1 = 0.0f, s2 = 0.0f;
    int k0 = h * 64;
#pragma unroll 8
    for (int k = k0; k < k0 + 64; k++) {
        float ev = er[k];
        s1 += ev * W[k * EMB + n];
        s2 += ev * W[(EMB + k) * EMB + n];
    }
    if (h) { p1[n] = s1; p2[n] = s2; }
    __syncthreads();
    if (!h) {
        g_EW1f[z * EMB + n] = s1 + p1[n] + b[n];
        g_EW2f[z * EMB + n] = s2 + p2[n];
    }
}

// ---------------- prep2: EWP[zi*95+zj][n] = fp16(EW1[zi][n]+EW2[zj][n]) ----------------
__global__ void prep2_kernel() {
    int p = blockIdx.x, n = threadIdx.x;
    int zi = p / N_ELEM, zj = p - zi * N_ELEM;
    g_EWPh[(size_t)p * EMB + n] =
        __float2half(g_EW1f[zi * EMB + n] + g_EW2f[zj * EMB + n]);
}

// ---------------- main fused edge kernel (also does x_0 copy) ----------------
__global__ void __launch_bounds__(THREADS, 2)
main_kernel(const int* __restrict__ Z, const float* __restrict__ rbf,
            const int* __restrict__ idx_i, const int* __restrict__ idx_j,
            const float* __restrict__ W_rbf, const float* __restrict__ b_rbf,
            const float* __restrict__ W, float* __restrict__ out,
            const float* __restrict__ emb, float* __restrict__ out0) {
    extern __shared__ char smem[];
    const int tid  = threadIdx.x;
    const int wid  = tid >> 5, lane = tid & 31;
    const int q    = lane >> 2, c = lane & 3;
    const int m0   = (wid & 3) * 32;     // warp's 32 rows (2 m-tiles)
    const int n0   = (wid >> 2) * 64;    // warp's n-half
    const int ntpb = n0 >> 4;            // global ntp base (0 or 4)
    const int half = lane >> 4, li = lane & 15;   // epilogue row-domain mapping

    // staging maps
    const int prow = tid >> 1, ph = tid & 1;     // rbf: 2 threads/row
    const int srp  = prow >> 4, sq = prow & 7, shi = (prow >> 3) & 1;

    // ---- x_0 = embeddings[Z] (independent; overlaps smem fills) ----
    for (int i = blockIdx.x * THREADS + tid; i < N_ATOMS_ * (EMB / 4);
         i += GRID_MAIN * THREADS) {
        int a = i >> 5, qq = i & 31;
        ((float4*)out0)[(size_t)a * 32 + qq] = ((const float4*)emb)[(size_t)Z[a] * 32 + qq];
    }

    // ---- one-time fills ----
    for (int idx = tid; idx < EMB * NRAD; idx += THREADS) {
        int n = idx & 127, k = idx >> 7;
        int nt1 = n >> 3, qn = n & 7, p = physmap(k);
        int cc = p >> 2, slot = p & 3, side = nt1 & 1, ntp = nt1 >> 1;
        __half h = __float2half(W_rbf[k * EMB + n]);
        *(unsigned short*)(smem + OFF_BT1 + ntp * 512 + qn * 64 + cc * 16 +
                           side * 8 + slot * 2) = __half_as_ushort(h);
    }
    for (int idx = tid; idx < EMB * EMB; idx += THREADS) {
        int n = idx & 127, k = idx >> 7;
        int ks = k >> 4, kk = k & 15, p = physmap(kk);
        int cc = p >> 2, slot = p & 3;
        int ntg = n >> 3, qn = n & 7, ntp = ntg >> 1, side = ntg & 1;
        __half h = __float2half(W[(2 * EMB + k) * EMB + n]);   // W3[k][n]
        *(unsigned short*)(smem + OFF_BT2 + ks * 4096 + ntp * 512 + qn * 64 + cc * 16 +
                           side * 8 + slot * 2) = __half_as_ushort(h);
    }
    if (tid < EMB) ((float*)(smem + OFF_BIAS))[tid] = b_rbf[tid];

    // ---- prologue: stage first tile into buffer 0 ----
    int t = blockIdx.x;
    {
        long eb = (long)t * TILE;
        long e  = eb + prow; if (e >= N_EDGES_) e = N_EDGES_ - 1;
        float4 a = ((const float4*)rbf)[e * 4 + ph];
        float4 b = ((const float4*)rbf)[e * 4 + ph + 2];
        char* rbb = smem + OFF_RBFH + srp * 512 + sq * 64 + shi * 8;
        *(uint2*)(rbb + (2 * ph) * 16)     = make_uint2(pack2(a.x, a.y), pack2(b.x, b.y));
        *(uint2*)(rbb + (2 * ph + 1) * 16) = make_uint2(pack2(a.z, a.w), pack2(b.z, b.w));
        if (tid < TILE) {
            long ez = eb + tid; if (ez >= N_EDGES_) ez = N_EDGES_ - 1;
            ((int*)(smem + OFF_ZP))[tid] = Z[idx_i[ez]] * N_ELEM + Z[idx_j[ez]];
        }
    }
    __syncthreads();

    char* scr = smem + OFF_SCR + wid * SCR_WARP;   // warp-private scratch

    int buf = 0;
    for (; t < NTILES; t += GRID_MAIN) {
        // ---- prefetch next tile's staging data ----
        float4 pa, pb; int pzp = 0;
        {
            int tn = t + GRID_MAIN;
            long eb = (long)(tn < NTILES ? tn : t) * TILE;
            long e  = eb + prow; if (e >= N_EDGES_) e = N_EDGES_ - 1;
            pa = ((const float4*)rbf)[e * 4 + ph];
            pb = ((const float4*)rbf)[e * 4 + ph + 2];
            if (tid < TILE) {
                long ez = eb + tid; if (ez >= N_EDGES_) ez = N_EDGES_ - 1;
                pzp = Z[idx_i[ez]] * N_ELEM + Z[idx_j[ez]];
            }
        }

        const long base = (long)t * TILE;
        const char* rb  = smem + OFF_RBFH + buf * 4096;
        const int* zp_s = (const int*)(smem + OFF_ZP + buf * 512);

        // ---- A operands for GEMM1: one LDS.128 per m-tile ----
        uint4 ar[2];
#pragma unroll
        for (int mt = 0; mt < 2; mt++)
            ar[mt] = *(const uint4*)(rb + (m0 / 16 + mt) * 512 + q * 64 + c * 16);

        // ---- fused GEMM1 -> silu -> GEMM2, one k-step at a time ----
        float dacc[2][8][4];
#pragma unroll
        for (int mt = 0; mt < 2; mt++)
#pragma unroll
            for (int nt = 0; nt < 8; nt++)
#pragma unroll
                for (int r = 0; r < 4; r++) dacc[mt][nt][r] = 0.0f;

        const float* bias_s = (const float*)(smem + OFF_BIAS);
#pragma unroll
        for (int ks = 0; ks < 8; ks++) {
            uint4 b1v = *(const uint4*)(smem + OFF_BT1 + ks * 512 + q * 64 + c * 16);
            float2 bb0 = *(const float2*)(bias_s + 16 * ks + 2 * c);
            float2 bb1 = *(const float2*)(bias_s + 16 * ks + 8 + 2 * c);
            uint32_t afrag[2][4];
#pragma unroll
            for (int mt = 0; mt < 2; mt++) {
                float d0[4] = {bb0.x, bb0.y, bb0.x, bb0.y};
                mma_f16(d0, ar[mt].x, ar[mt].z, ar[mt].y, ar[mt].w, b1v.x, b1v.y);
                afrag[mt][0] = pack2(silu_tanh(d0[0]), silu_tanh(d0[1]));
                afrag[mt][1] = pack2(silu_tanh(d0[2]), silu_tanh(d0[3]));
                float d1[4] = {bb1.x, bb1.y, bb1.x, bb1.y};
                mma_f16(d1, ar[mt].x, ar[mt].z, ar[mt].y, ar[mt].w, b1v.z, b1v.w);
                afrag[mt][2] = pack2(silu_tanh(d1[0]), silu_tanh(d1[1]));
                afrag[mt][3] = pack2(silu_tanh(d1[2]), silu_tanh(d1[3]));
            }
#pragma unroll
            for (int ntp = 0; ntp < 4; ntp++) {
                uint4 bv = *(const uint4*)(smem + OFF_BT2 + ks * 4096 +
                                           (ntpb + ntp) * 512 + q * 64 + c * 16);
                mma_f16(dacc[0][2 * ntp],     afrag[0][0], afrag[0][1], afrag[0][2],
                        afrag[0][3], bv.x, bv.y);
                mma_f16(dacc[1][2 * ntp],     afrag[1][0], afrag[1][1], afrag[1][2],
                        afrag[1][3], bv.x, bv.y);
                mma_f16(dacc[0][2 * ntp + 1], afrag[0][0], afrag[0][1], afrag[0][2],
                        afrag[0][3], bv.z, bv.w);
                mma_f16(dacc[1][2 * ntp + 1], afrag[1][0], afrag[1][1], afrag[1][2],
                        afrag[1][3], bv.z, bv.w);
            }
        }

        // ---- epilogue: warp-private transpose -> row-domain EW+silu -> coalesced STG ----
#pragma unroll
        for (int mt = 0; mt < 2; mt++) {
            // scatter fragments into scratch (rows local 0..15, cols local 0..63)
#pragma unroll
            for (int nt = 0; nt < 8; nt++) {
                *(float2*)(scr + q * 272 + (8 * nt + 2 * c) * 4) =
                    make_float2(dacc[mt][nt][0], dacc[mt][nt][1]);
                *(float2*)(scr + (q + 8) * 272 + (8 * nt + 2 * c) * 4) =
                    make_float2(dacc[mt][nt][2], dacc[mt][nt][3]);
            }
            __syncwarp();
            // readback 2 rows per instruction; coalesced gather + store
#pragma unroll
            for (int i = 0; i < 8; i++) {
                int rl = 2 * i + half;
                int r  = m0 + 16 * mt + rl;
                float4 v = *(const float4*)(scr + rl * 272 + li * 16);
                int zp = zp_s[r];
                uint2 ue = *(const uint2*)(g_EWPh + (size_t)zp * EMB + n0 + 4 * li);
                float2 f01 = __half22float2(*(const __half2*)&ue.x);
                float2 f23 = __half22float2(*(const __half2*)&ue.y);
                float4 o;
                o.x = silu_tanh(v.x + f01.x);
                o.y = silu_tanh(v.y + f01.y);
                o.z = silu_tanh(v.z + f23.x);
                o.w = silu_tanh(v.w + f23.y);
                long e = base + r;
                if (e < N_EDGES_)
                    *(float4*)(out + (size_t)e * EMB + n0 + 4 * li) = o;
            }
            __syncwarp();
        }

        // ---- store prefetched staging data into the other buffer ----
        {
            int nb = buf ^ 1;
            char* rbb = smem + OFF_RBFH + nb * 4096 + srp * 512 + sq * 64 + shi * 8;
            *(uint2*)(rbb + (2 * ph) * 16)     = make_uint2(pack2(pa.x, pa.y), pack2(pb.x, pb.y));
            *(uint2*)(rbb + (2 * ph + 1) * 16) = make_uint2(pack2(pa.z, pa.w), pack2(pb.z, pb.w));
            if (tid < TILE) ((int*)(smem + OFF_ZP + nb * 512))[tid] = pzp;
        }
        __syncthreads();
        buf ^= 1;
    }
}

// ---------------- launch ----------------
extern "C" void kernel_launch(void* const* d_in, const int* in_sizes, int n_in,
                              void* d_out, int out_size) {
    (void)in_sizes; (void)n_in; (void)out_size;
    const int*   Z     = (const int*)d_in[0];
    const float* rbf   = (const float*)d_in[1];
    const int*   idx_i = (const int*)d_in[2];
    const int*   idx_j = (const int*)d_in[3];
    const float* emb   = (const float*)d_in[4];
    const float* W_rbf = (const float*)d_in[5];
    const float* b_rbf = (const float*)d_in[6];
    const float* W     = (const float*)d_in[7];
    const float* b     = (const float*)d_in[8];
    float* out  = (float*)d_out;
    float* out0 = out + (size_t)N_EDGES_ * EMB;

    cudaFuncSetAttribute(main_kernel, cudaFuncAttributeMaxDynamicSharedMemorySize,
                         SMEM_DYN);
    prep_kernel<<<N_ELEM, 256>>>(emb, W, b);
    prep2_kernel<<<N_ELEM * N_ELEM, EMB>>>();
    main_kernel<<<GRID_MAIN, THREADS, SMEM_DYN>>>(Z, rbf, idx_i, idx_j, W_rbf, b_rbf,
                                                  W, out, emb, out0);
}

// round 14
// speedup vs baseline: 1.2450x; 1.2450x over previous
#include <cuda_runtime.h>
#include <cuda_fp16.h>
#include <cstdint>

#define EMB      128
#define NRAD     16
#define N_ATOMS_ 100000
#define N_EDGES_ 1000000
#define N_ELEM   95
#define TILE     128
#define NTILES   ((N_EDGES_ + TILE - 1) / TILE)   // 7813
#define GRID_MAIN 296
#define THREADS  256

// ---------------- smem layout (bytes) ----------------
#define OFF_BT2   0                    // W3^T fp16 frags [ks(8)][ntp(4x2)][q(8)][c(4)]x16B = 32KB
#define OFF_BT1   32768                // W_rbf^T fp16 frags = 4KB
#define OFF_RBFH  36864                // rbf tile fp16 A-frags, x2 buffers = 8KB
#define OFF_BIAS  45056                // b_rbf [128] f32
#define OFF_ZP    45568                // zp pair-index [128] int, x2 buffers = 1KB
#define SMEM_TOTAL 46592

// prep1 fp32 projections; prep2 merged fp16 pair table, PERMUTATION-swizzled:
// physical col n = 64*nh + 16*j + 4*c + 2*nto + b
//   -> pos = p*128 + nh*64 + c*16 + j*4 + nto*2 + b
__device__ float g_EW1f[N_ELEM * EMB];
__device__ float g_EW2f[N_ELEM * EMB];
__device__ __align__(16) __half g_EWPh[N_ELEM * N_ELEM * EMB];   // 2.31MB

// ---------------- helpers ----------------
__device__ __forceinline__ float silu_tanh(float x) {
    float t;
    asm("tanh.approx.f32 %0, %1;" : "=f"(t) : "f"(0.5f * x));
    return 0.5f * x * (1.0f + t);
}
__device__ __forceinline__ uint32_t pack2(float lo, float hi) {
    uint32_t r;
    asm("cvt.rn.f16x2.f32 %0, %1, %2;" : "=r"(r) : "f"(hi), "f"(lo));
    return r;
}
__device__ __forceinline__ void mma_f16(float* d,
    uint32_t a0, uint32_t a1, uint32_t a2, uint32_t a3,
    uint32_t b0, uint32_t b1) {
    asm volatile(
        "mma.sync.aligned.m16n8k16.row.col.f32.f16.f16.f32 "
        "{%0,%1,%2,%3}, {%4,%5,%6,%7}, {%8,%9}, {%0,%1,%2,%3};"
        : "+f"(d[0]), "+f"(d[1]), "+f"(d[2]), "+f"(d[3])
        : "r"(a0), "r"(a1), "r"(a2), "r"(a3), "r"(b0), "r"(b1));
}
__device__ __forceinline__ int physmap(int kk) {
    return 4 * ((kk & 7) >> 1) + 2 * (kk >> 3) + (kk & 1);
}

// ---------------- prep1: EW1f = emb@W1 + b, EW2f = emb@W2 (fp32 linear) ----------------
__global__ void prep_kernel(const float* __restrict__ emb, const float* __restrict__ W,
                            const float* __restrict__ b) {
    __shared__ float p1[EMB], p2[EMB];
    int z = blockIdx.x, n = threadIdx.x & 127, h = threadIdx.x >> 7;
    const float* er = emb + z * EMB;
    float s1 = 0.0f, s2 = 0.0f;
    int k0 = h * 64;
#pragma unroll 8
    for (int k = k0; k < k0 + 64; k++) {
        float ev = er[k];
        s1 += ev * W[k * EMB + n];
        s2 += ev * W[(EMB + k) * EMB + n];
    }
    if (h) { p1[n] = s1; p2[n] = s2; }
    __syncthreads();
    if (!h) {
        g_EW1f[z * EMB + n] = s1 + p1[n] + b[n];
        g_EW2f[z * EMB + n] = s2 + p2[n];
    }
}

// ---------------- prep2: EWP (merged pair table), permutation-swizzled ----------------
__global__ void prep2_kernel() {
    int p = blockIdx.x, n = threadIdx.x;
    int zi = p / N_ELEM, zj = p - zi * N_ELEM;
    float v = g_EW1f[zi * EMB + n] + g_EW2f[zj * EMB + n];
    int nh = n >> 6, m = n & 63;
    int j = m >> 4, c4 = (m >> 2) & 3, nto = (m >> 1) & 1, bb = m & 1;
    g_EWPh[(size_t)p * EMB + nh * 64 + c4 * 16 + j * 4 + nto * 2 + bb] = __float2half(v);
}

// ---------------- main fused edge kernel (also does x_0 copy) ----------------
__global__ void __launch_bounds__(THREADS, 2)
main_kernel(const int* __restrict__ Z, const float* __restrict__ rbf,
            const int* __restrict__ idx_i, const int* __restrict__ idx_j,
            const float* __restrict__ W_rbf, const float* __restrict__ b_rbf,
            const float* __restrict__ W, float* __restrict__ out,
            const float* __restrict__ emb, float* __restrict__ out0) {
    __shared__ char smem[SMEM_TOTAL];
    const int tid  = threadIdx.x;
    const int wid  = tid >> 5, lane = tid & 31;
    const int q    = lane >> 2, c = lane & 3;
    const int m0   = (wid & 3) * 32;     // warp's 32 rows (2 m-tiles)
    const int n0   = (wid >> 2) * 64;    // warp's n-half
    const int ntpb = n0 >> 4;            // global ntp base (0 or 4)

    // staging maps
    const int prow = tid >> 1, ph = tid & 1;     // rbf: 2 threads/row
    const int srp  = prow >> 4, sq = prow & 7, shi = (prow >> 3) & 1;

    // ---- x_0 = embeddings[Z] (independent; overlaps smem fills) ----
    for (int i = blockIdx.x * THREADS + tid; i < N_ATOMS_ * (EMB / 4);
         i += GRID_MAIN * THREADS) {
        int a = i >> 5, qq = i & 31;
        ((float4*)out0)[(size_t)a * 32 + qq] = ((const float4*)emb)[(size_t)Z[a] * 32 + qq];
    }

    // ---- one-time fills ----
    for (int idx = tid; idx < EMB * NRAD; idx += THREADS) {
        int n = idx & 127, k = idx >> 7;
        int nt1 = n >> 3, qn = n & 7, p = physmap(k);
        int cc = p >> 2, slot = p & 3, side = nt1 & 1, ntp = nt1 >> 1;
        __half h = __float2half(W_rbf[k * EMB + n]);
        *(unsigned short*)(smem + OFF_BT1 + ntp * 512 + qn * 64 + cc * 16 +
                           side * 8 + slot * 2) = __half_as_ushort(h);
    }
    // BT2: W3^T with N-PERMUTATION: physical col n -> logical tile g, in-tile qB
    for (int idx = tid; idx < EMB * EMB; idx += THREADS) {
        int n = idx & 127, k = idx >> 7;
        int ks = k >> 4, kk = k & 15, p = physmap(kk);
        int cc = p >> 2, slot = p & 3;
        int nh = n >> 6, m = n & 63;
        int j = m >> 4, c4 = (m >> 2) & 3, nto = (m >> 1) & 1, bb = m & 1;
        int g  = nh * 8 + 2 * j + nto;      // global logical n8-tile
        int qB = 2 * c4 + bb;               // in-tile n index
        __half h = __float2half(W[(2 * EMB + k) * EMB + n]);   // W3[k][n]
        *(unsigned short*)(smem + OFF_BT2 + ks * 4096 + (g >> 1) * 512 + qB * 64 +
                           cc * 16 + (g & 1) * 8 + slot * 2) = __half_as_ushort(h);
    }
    if (tid < EMB) ((float*)(smem + OFF_BIAS))[tid] = b_rbf[tid];

    // ---- prologue: stage first tile into buffer 0 ----
    int t = blockIdx.x;
    {
        long eb = (long)t * TILE;
        long e  = eb + prow; if (e >= N_EDGES_) e = N_EDGES_ - 1;
        float4 a = ((const float4*)rbf)[e * 4 + ph];
        float4 b = ((const float4*)rbf)[e * 4 + ph + 2];
        char* rbb = smem + OFF_RBFH + srp * 512 + sq * 64 + shi * 8;
        *(uint2*)(rbb + (2 * ph) * 16)     = make_uint2(pack2(a.x, a.y), pack2(b.x, b.y));
        *(uint2*)(rbb + (2 * ph + 1) * 16) = make_uint2(pack2(a.z, a.w), pack2(b.z, b.w));
        if (tid < TILE) {
            long ez = eb + tid; if (ez >= N_EDGES_) ez = N_EDGES_ - 1;
            ((int*)(smem + OFF_ZP))[tid] = Z[idx_i[ez]] * N_ELEM + Z[idx_j[ez]];
        }
    }
    __syncthreads();

    int buf = 0;
    for (; t < NTILES; t += GRID_MAIN) {
        // ---- prefetch next tile's staging data ----
        float4 pa, pb; int pzp = 0;
        {
            int tn = t + GRID_MAIN;
            long eb = (long)(tn < NTILES ? tn : t) * TILE;
            long e  = eb + prow; if (e >= N_EDGES_) e = N_EDGES_ - 1;
            pa = ((const float4*)rbf)[e * 4 + ph];
            pb = ((const float4*)rbf)[e * 4 + ph + 2];
            if (tid < TILE) {
                long ez = eb + tid; if (ez >= N_EDGES_) ez = N_EDGES_ - 1;
                pzp = Z[idx_i[ez]] * N_ELEM + Z[idx_j[ez]];
            }
        }

        const long base = (long)t * TILE;
        const char* rb  = smem + OFF_RBFH + buf * 4096;
        const int* zp_s = (const int*)(smem + OFF_ZP + buf * 512);

        // ---- A operands for GEMM1: one LDS.128 per m-tile ----
        uint4 ar[2];
#pragma unroll
        for (int mt = 0; mt < 2; mt++)
            ar[mt] = *(const uint4*)(rb + (m0 / 16 + mt) * 512 + q * 64 + c * 16);

        // ---- fused GEMM1 -> silu -> GEMM2, one k-step at a time ----
        float dacc[2][8][4];
#pragma unroll
        for (int mt = 0; mt < 2; mt++)
#pragma unroll
            for (int nt = 0; nt < 8; nt++)
#pragma unroll
                for (int r = 0; r < 4; r++) dacc[mt][nt][r] = 0.0f;

        const float* bias_s = (const float*)(smem + OFF_BIAS);
#pragma unroll
        for (int ks = 0; ks < 8; ks++) {
            uint4 b1v = *(const uint4*)(smem + OFF_BT1 + ks * 512 + q * 64 + c * 16);
            float2 bb0 = *(const float2*)(bias_s + 16 * ks + 2 * c);
            float2 bb1 = *(const float2*)(bias_s + 16 * ks + 8 + 2 * c);
            uint32_t afrag[2][4];
#pragma unroll
            for (int mt = 0; mt < 2; mt++) {
                float d0[4] = {bb0.x, bb0.y, bb0.x, bb0.y};
                mma_f16(d0, ar[mt].x, ar[mt].z, ar[mt].y, ar[mt].w, b1v.x, b1v.y);
                afrag[mt][0] = pack2(silu_tanh(d0[0]), silu_tanh(d0[1]));
                afrag[mt][1] = pack2(silu_tanh(d0[2]), silu_tanh(d0[3]));
                float d1[4] = {bb1.x, bb1.y, bb1.x, bb1.y};
                mma_f16(d1, ar[mt].x, ar[mt].z, ar[mt].y, ar[mt].w, b1v.z, b1v.w);
                afrag[mt][2] = pack2(silu_tanh(d1[0]), silu_tanh(d1[1]));
                afrag[mt][3] = pack2(silu_tanh(d1[2]), silu_tanh(d1[3]));
            }
#pragma unroll
            for (int ntp = 0; ntp < 4; ntp++) {
                uint4 bv = *(const uint4*)(smem + OFF_BT2 + ks * 4096 +
                                           (ntpb + ntp) * 512 + q * 64 + c * 16);
                mma_f16(dacc[0][2 * ntp],     afrag[0][0], afrag[0][1], afrag[0][2],
                        afrag[0][3], bv.x, bv.y);
                mma_f16(dacc[1][2 * ntp],     afrag[1][0], afrag[1][1], afrag[1][2],
                        afrag[1][3], bv.x, bv.y);
                mma_f16(dacc[0][2 * ntp + 1], afrag[0][0], afrag[0][1], afrag[0][2],
                        afrag[0][3], bv.z, bv.w);
                mma_f16(dacc[1][2 * ntp + 1], afrag[1][0], afrag[1][1], afrag[1][2],
                        afrag[1][3], bv.z, bv.w);
            }
        }

        // ---- epilogue: permuted cols -> STG.128; EWP gather 2x LDG.128 ----
        // dacc tile nt=2j+nto, value b at physical col n0 + 16j + 4c + 2nto + b
#pragma unroll
        for (int mt = 0; mt < 2; mt++) {
#pragma unroll
            for (int sub = 0; sub < 2; sub++) {
                int r = m0 + 16 * mt + 8 * sub + q;
                long e = base + r;
                if (e < N_EDGES_) {
                    int zp = zp_s[r];
                    const __half* hp = g_EWPh + (size_t)zp * EMB + n0 + c * 16;
                    uint4 u0 = *(const uint4*)(hp);        // j=0 (x,y), j=1 (z,w)
                    uint4 u1 = *(const uint4*)(hp + 8);    // j=2 (x,y), j=3 (z,w)
                    float* op = out + (size_t)e * EMB + n0 + 4 * c;
                    uint32_t uh[8] = {u0.x, u0.y, u0.z, u0.w, u1.x, u1.y, u1.z, u1.w};
#pragma unroll
                    for (int j = 0; j < 4; j++) {
                        float2 fa = __half22float2(*(const __half2*)&uh[2 * j]);
                        float2 fb = __half22float2(*(const __half2*)&uh[2 * j + 1]);
                        float4 o;
                        o.x = silu_tanh(dacc[mt][2 * j][2 * sub + 0] + fa.x);
                        o.y = silu_tanh(dacc[mt][2 * j][2 * sub + 1] + fa.y);
                        o.z = silu_tanh(dacc[mt][2 * j + 1][2 * sub + 0] + fb.x);
                        o.w = silu_tanh(dacc[mt][2 * j + 1][2 * sub + 1] + fb.y);
                        *(float4*)(op + 16 * j) = o;
                    }
                }
            }
        }

        // ---- store prefetched staging data into the other buffer ----
        {
            int nb = buf ^ 1;
            char* rbb = smem + OFF_RBFH + nb * 4096 + srp * 512 + sq * 64 + shi * 8;
            *(uint2*)(rbb + (2 * ph) * 16)     = make_uint2(pack2(pa.x, pa.y), pack2(pb.x, pb.y));
            *(uint2*)(rbb + (2 * ph + 1) * 16) = make_uint2(pack2(pa.z, pa.w), pack2(pb.z, pb.w));
            if (tid < TILE) ((int*)(smem + OFF_ZP + nb * 512))[tid] = pzp;
        }
        __syncthreads();
        buf ^= 1;
    }
}

// ---------------- launch ----------------
extern "C" void kernel_launch(void* const* d_in, const int* in_sizes, int n_in,
                              void* d_out, int out_size) {
    (void)in_sizes; (void)n_in; (void)out_size;
    const int*   Z     = (const int*)d_in[0];
    const float* rbf   = (const float*)d_in[1];
    const int*   idx_i = (const int*)d_in[2];
    const int*   idx_j = (const int*)d_in[3];
    const float* emb   = (const float*)d_in[4];
    const float* W_rbf = (const float*)d_in[5];
    const float* b_rbf = (const float*)d_in[6];
    const float* W     = (const float*)d_in[7];
    const float* b     = (const float*)d_in[8];
    float* out  = (float*)d_out;
    float* out0 = out + (size_t)N_EDGES_ * EMB;

    prep_kernel<<<N_ELEM, 256>>>(emb, W, b);
    prep2_kernel<<<N_ELEM * N_ELEM, EMB>>>();
    main_kernel<<<GRID_MAIN, THREADS>>>(Z, rbf, idx_i, idx_j, W_rbf, b_rbf, W, out,
                                        emb, out0);
}

// round 15
// speedup vs baseline: 1.2706x; 1.0206x over previous
#include <cuda_runtime.h>
#include <cuda_fp16.h>
#include <cstdint>

#define EMB      128
#define NRAD     16
#define N_ATOMS_ 100000
#define N_EDGES_ 1000000
#define N_ELEM   95
#define TILE     128
#define NTILES   ((N_EDGES_ + TILE - 1) / TILE)   // 7813
#define GRID_MAIN 296
#define THREADS  256

// ---------------- smem layout (bytes) ----------------
#define OFF_BT2   0                    // W3^T fp16 frags [ks(8)][ntp(4x2)][q(8)][c(4)]x16B = 32KB
#define OFF_BT1   32768                // W_rbf^T fp16 frags = 4KB
#define OFF_RBFH  36864                // rbf tile fp16 A-frags, x2 buffers = 8KB
#define OFF_BIAS  45056                // b_rbf [128] f32
#define OFF_ZP    45568                // zp pair-index [128] int, x2 buffers = 1KB
#define SMEM_TOTAL 46592

// prep1 fp32 projections; prep2 merged fp16 pair table, PERMUTATION-swizzled:
// physical col n = 64*nh + 16*j + 4*c + 2*nto + b
//   -> pos = p*128 + nh*64 + c*16 + j*4 + nto*2 + b
__device__ float g_EW1f[N_ELEM * EMB];
__device__ float g_EW2f[N_ELEM * EMB];
__device__ __align__(16) __half g_EWPh[N_ELEM * N_ELEM * EMB];   // 2.31MB

// ---------------- helpers ----------------
__device__ __forceinline__ float silu_tanh(float x) {
    float t;
    asm("tanh.approx.f32 %0, %1;" : "=f"(t) : "f"(0.5f * x));
    return 0.5f * x * (1.0f + t);
}
__device__ __forceinline__ uint32_t pack2(float lo, float hi) {
    uint32_t r;
    asm("cvt.rn.f16x2.f32 %0, %1, %2;" : "=r"(r) : "f"(hi), "f"(lo));
    return r;
}
// packed fp16 silu for GEMM1: one MUFU for two lanes.
// hx = 0.5*x; r = hx * (1 + tanh(hx))  == x*sigmoid(x)
__device__ __forceinline__ uint32_t silu2_f16(float lo, float hi) {
    uint32_t x = pack2(lo, hi), hx, t;
    asm("mul.rn.f16x2 %0, %1, %2;" : "=r"(hx) : "r"(x), "r"(0x38003800u));  // {0.5,0.5}
    asm("tanh.approx.f16x2 %0, %1;" : "=r"(t) : "r"(hx));
    asm("add.rn.f16x2 %0, %1, %2;" : "=r"(t) : "r"(t), "r"(0x3C003C00u));   // +{1,1}
    asm("mul.rn.f16x2 %0, %1, %2;" : "=r"(hx) : "r"(hx), "r"(t));
    return hx;
}
__device__ __forceinline__ void mma_f16(float* d,
    uint32_t a0, uint32_t a1, uint32_t a2, uint32_t a3,
    uint32_t b0, uint32_t b1) {
    asm volatile(
        "mma.sync.aligned.m16n8k16.row.col.f32.f16.f16.f32 "
        "{%0,%1,%2,%3}, {%4,%5,%6,%7}, {%8,%9}, {%0,%1,%2,%3};"
        : "+f"(d[0]), "+f"(d[1]), "+f"(d[2]), "+f"(d[3])
        : "r"(a0), "r"(a1), "r"(a2), "r"(a3), "r"(b0), "r"(b1));
}
__device__ __forceinline__ int physmap(int kk) {
    return 4 * ((kk & 7) >> 1) + 2 * (kk >> 3) + (kk & 1);
}

// ---------------- prep1: EW1f = emb@W1 + b, EW2f = emb@W2 (fp32 linear) ----------------
__global__ void prep_kernel(const float* __restrict__ emb, const float* __restrict__ W,
                            const float* __restrict__ b) {
    __shared__ float p1[EMB], p2[EMB];
    int z = blockIdx.x, n = threadIdx.x & 127, h = threadIdx.x >> 7;
    const float* er = emb + z * EMB;
    float s1 = 0.0f, s2 = 0.0f;
    int k0 = h * 64;
#pragma unroll 8
    for (int k = k0; k < k0 + 64; k++) {
        float ev = er[k];
        s1 += ev * W[k * EMB + n];
        s2 += ev * W[(EMB + k) * EMB + n];
    }
    if (h) { p1[n] = s1; p2[n] = s2; }
    __syncthreads();
    if (!h) {
        g_EW1f[z * EMB + n] = s1 + p1[n] + b[n];
        g_EW2f[z * EMB + n] = s2 + p2[n];
    }
}

// ---------------- prep2: EWP (merged pair table), permutation-swizzled ----------------
__global__ void prep2_kernel() {
    int p = blockIdx.x, n = threadIdx.x;
    int zi = p / N_ELEM, zj = p - zi * N_ELEM;
    float v = g_EW1f[zi * EMB + n] + g_EW2f[zj * EMB + n];
    int nh = n >> 6, m = n & 63;
    int j = m >> 4, c4 = (m >> 2) & 3, nto = (m >> 1) & 1, bb = m & 1;
    g_EWPh[(size_t)p * EMB + nh * 64 + c4 * 16 + j * 4 + nto * 2 + bb] = __float2half(v);
}

// ---------------- main fused edge kernel (also does x_0 copy) ----------------
__global__ void __launch_bounds__(THREADS, 2)
main_kernel(const int* __restrict__ Z, const float* __restrict__ rbf,
            const int* __restrict__ idx_i, const int* __restrict__ idx_j,
            const float* __restrict__ W_rbf, const float* __restrict__ b_rbf,
            const float* __restrict__ W, float* __restrict__ out,
            const float* __restrict__ emb, float* __restrict__ out0) {
    __shared__ char smem[SMEM_TOTAL];
    const int tid  = threadIdx.x;
    const int wid  = tid >> 5, lane = tid & 31;
    const int q    = lane >> 2, c = lane & 3;
    const int m0   = (wid & 3) * 32;     // warp's 32 rows (2 m-tiles)
    const int n0   = (wid >> 2) * 64;    // warp's n-half
    const int ntpb = n0 >> 4;            // global ntp base (0 or 4)

    // staging maps
    const int prow = tid >> 1, ph = tid & 1;     // rbf: 2 threads/row
    const int srp  = prow >> 4, sq = prow & 7, shi = (prow >> 3) & 1;

    // ---- x_0 = embeddings[Z] (independent; overlaps smem fills) ----
    for (int i = blockIdx.x * THREADS + tid; i < N_ATOMS_ * (EMB / 4);
         i += GRID_MAIN * THREADS) {
        int a = i >> 5, qq = i & 31;
        ((float4*)out0)[(size_t)a * 32 + qq] = ((const float4*)emb)[(size_t)Z[a] * 32 + qq];
    }

    // ---- one-time fills ----
    for (int idx = tid; idx < EMB * NRAD; idx += THREADS) {
        int n = idx & 127, k = idx >> 7;
        int nt1 = n >> 3, qn = n & 7, p = physmap(k);
        int cc = p >> 2, slot = p & 3, side = nt1 & 1, ntp = nt1 >> 1;
        __half h = __float2half(W_rbf[k * EMB + n]);
        *(unsigned short*)(smem + OFF_BT1 + ntp * 512 + qn * 64 + cc * 16 +
                           side * 8 + slot * 2) = __half_as_ushort(h);
    }
    // BT2: W3^T with N-PERMUTATION: physical col n -> logical tile g, in-tile qB
    for (int idx = tid; idx < EMB * EMB; idx += THREADS) {
        int n = idx & 127, k = idx >> 7;
        int ks = k >> 4, kk = k & 15, p = physmap(kk);
        int cc = p >> 2, slot = p & 3;
        int nh = n >> 6, m = n & 63;
        int j = m >> 4, c4 = (m >> 2) & 3, nto = (m >> 1) & 1, bb = m & 1;
        int g  = nh * 8 + 2 * j + nto;      // global logical n8-tile
        int qB = 2 * c4 + bb;               // in-tile n index
        __half h = __float2half(W[(2 * EMB + k) * EMB + n]);   // W3[k][n]
        *(unsigned short*)(smem + OFF_BT2 + ks * 4096 + (g >> 1) * 512 + qB * 64 +
                           cc * 16 + (g & 1) * 8 + slot * 2) = __half_as_ushort(h);
    }
    if (tid < EMB) ((float*)(smem + OFF_BIAS))[tid] = b_rbf[tid];

    // ---- prologue: stage first tile into buffer 0 ----
    int t = blockIdx.x;
    {
        long eb = (long)t * TILE;
        long e  = eb + prow; if (e >= N_EDGES_) e = N_EDGES_ - 1;
        float4 a = ((const float4*)rbf)[e * 4 + ph];
        float4 b = ((const float4*)rbf)[e * 4 + ph + 2];
        char* rbb = smem + OFF_RBFH + srp * 512 + sq * 64 + shi * 8;
        *(uint2*)(rbb + (2 * ph) * 16)     = make_uint2(pack2(a.x, a.y), pack2(b.x, b.y));
        *(uint2*)(rbb + (2 * ph + 1) * 16) = make_uint2(pack2(a.z, a.w), pack2(b.z, b.w));
        if (tid < TILE) {
            long ez = eb + tid; if (ez >= N_EDGES_) ez = N_EDGES_ - 1;
            ((int*)(smem + OFF_ZP))[tid] = Z[idx_i[ez]] * N_ELEM + Z[idx_j[ez]];
        }
    }
    __syncthreads();

    int buf = 0;
    for (; t < NTILES; t += GRID_MAIN) {
        // ---- prefetch next tile's staging data ----
        float4 pa, pb; int pzp = 0;
        {
            int tn = t + GRID_MAIN;
            long eb = (long)(tn < NTILES ? tn : t) * TILE;
            long e  = eb + prow; if (e >= N_EDGES_) e = N_EDGES_ - 1;
            pa = ((const float4*)rbf)[e * 4 + ph];
            pb = ((const float4*)rbf)[e * 4 + ph + 2];
            if (tid < TILE) {
                long ez = eb + tid; if (ez >= N_EDGES_) ez = N_EDGES_ - 1;
                pzp = Z[idx_i[ez]] * N_ELEM + Z[idx_j[ez]];
            }
        }

        const long base = (long)t * TILE;
        const char* rb  = smem + OFF_RBFH + buf * 4096;
        const int* zp_s = (const int*)(smem + OFF_ZP + buf * 512);

        // ---- A operands for GEMM1: one LDS.128 per m-tile ----
        uint4 ar[2];
#pragma unroll
        for (int mt = 0; mt < 2; mt++)
            ar[mt] = *(const uint4*)(rb + (m0 / 16 + mt) * 512 + q * 64 + c * 16);

        // ---- fused GEMM1 -> silu(f16x2) -> GEMM2, one k-step at a time ----
        float dacc[2][8][4];
#pragma unroll
        for (int mt = 0; mt < 2; mt++)
#pragma unroll
            for (int nt = 0; nt < 8; nt++)
#pragma unroll
                for (int r = 0; r < 4; r++) dacc[mt][nt][r] = 0.0f;

        const float* bias_s = (const float*)(smem + OFF_BIAS);
#pragma unroll
        for (int ks = 0; ks < 8; ks++) {
            uint4 b1v = *(const uint4*)(smem + OFF_BT1 + ks * 512 + q * 64 + c * 16);
            float2 bb0 = *(const float2*)(bias_s + 16 * ks + 2 * c);
            float2 bb1 = *(const float2*)(bias_s + 16 * ks + 8 + 2 * c);
            uint32_t afrag[2][4];
#pragma unroll
            for (int mt = 0; mt < 2; mt++) {
                float d0[4] = {bb0.x, bb0.y, bb0.x, bb0.y};
                mma_f16(d0, ar[mt].x, ar[mt].z, ar[mt].y, ar[mt].w, b1v.x, b1v.y);
                afrag[mt][0] = silu2_f16(d0[0], d0[1]);
                afrag[mt][1] = silu2_f16(d0[2], d0[3]);
                float d1[4] = {bb1.x, bb1.y, bb1.x, bb1.y};
                mma_f16(d1, ar[mt].x, ar[mt].z, ar[mt].y, ar[mt].w, b1v.z, b1v.w);
                afrag[mt][2] = silu2_f16(d1[0], d1[1]);
                afrag[mt][3] = silu2_f16(d1[2], d1[3]);
            }
#pragma unroll
            for (int ntp = 0; ntp < 4; ntp++) {
                uint4 bv = *(const uint4*)(smem + OFF_BT2 + ks * 4096 +
                                           (ntpb + ntp) * 512 + q * 64 + c * 16);
                mma_f16(dacc[0][2 * ntp],     afrag[0][0], afrag[0][1], afrag[0][2],
                        afrag[0][3], bv.x, bv.y);
                mma_f16(dacc[1][2 * ntp],     afrag[1][0], afrag[1][1], afrag[1][2],
                        afrag[1][3], bv.x, bv.y);
                mma_f16(dacc[0][2 * ntp + 1], afrag[0][0], afrag[0][1], afrag[0][2],
                        afrag[0][3], bv.z, bv.w);
                mma_f16(dacc[1][2 * ntp + 1], afrag[1][0], afrag[1][1], afrag[1][2],
                        afrag[1][3], bv.z, bv.w);
            }
        }

        // ---- epilogue: permuted cols -> STG.128; EWP gather 2x LDG.128 ----
#pragma unroll
        for (int mt = 0; mt < 2; mt++) {
#pragma unroll
            for (int sub = 0; sub < 2; sub++) {
                int r = m0 + 16 * mt + 8 * sub + q;
                long e = base + r;
                if (e < N_EDGES_) {
                    int zp = zp_s[r];
                    const __half* hp = g_EWPh + (size_t)zp * EMB + n0 + c * 16;
                    uint4 u0 = *(const uint4*)(hp);
                    uint4 u1 = *(const uint4*)(hp + 8);
                    float* op = out + (size_t)e * EMB + n0 + 4 * c;
                    uint32_t uh[8] = {u0.x, u0.y, u0.z, u0.w, u1.x, u1.y, u1.z, u1.w};
#pragma unroll
                    for (int j = 0; j < 4; j++) {
                        float2 fa = __half22float2(*(const __half2*)&uh[2 * j]);
                        float2 fb = __half22float2(*(const __half2*)&uh[2 * j + 1]);
                        float4 o;
                        o.x = silu_tanh(dacc[mt][2 * j][2 * sub + 0] + fa.x);
                        o.y = silu_tanh(dacc[mt][2 * j][2 * sub + 1] + fa.y);
                        o.z = silu_tanh(dacc[mt][2 * j + 1][2 * sub + 0] + fb.x);
                        o.w = silu_tanh(dacc[mt][2 * j + 1][2 * sub + 1] + fb.y);
                        *(float4*)(op + 16 * j) = o;
                    }
                }
            }
        }

        // ---- store prefetched staging data into the other buffer ----
        {
            int nb = buf ^ 1;
            char* rbb = smem + OFF_RBFH + nb * 4096 + srp * 512 + sq * 64 + shi * 8;
            *(uint2*)(rbb + (2 * ph) * 16)     = make_uint2(pack2(pa.x, pa.y), pack2(pb.x, pb.y));
            *(uint2*)(rbb + (2 * ph + 1) * 16) = make_uint2(pack2(pa.z, pa.w), pack2(pb.z, pb.w));
            if (tid < TILE) ((int*)(smem + OFF_ZP + nb * 512))[tid] = pzp;
        }
        __syncthreads();
        buf ^= 1;
    }
}

// ---------------- launch ----------------
extern "C" void kernel_launch(void* const* d_in, const int* in_sizes, int n_in,
                              void* d_out, int out_size) {
    (void)in_sizes; (void)n_in; (void)out_size;
    const int*   Z     = (const int*)d_in[0];
    const float* rbf   = (const float*)d_in[1];
    const int*   idx_i = (const int*)d_in[2];
    const int*   idx_j = (const int*)d_in[3];
    const float* emb   = (const float*)d_in[4];
    const float* W_rbf = (const float*)d_in[5];
    const float* b_rbf = (const float*)d_in[6];
    const float* W     = (const float*)d_in[7];
    const float* b     = (const float*)d_in[8];
    float* out  = (float*)d_out;
    float* out0 = out + (size_t)N_EDGES_ * EMB;

    prep_kernel<<<N_ELEM, 256>>>(emb, W, b);
    prep2_kernel<<<N_ELEM * N_ELEM, EMB>>>();
    main_kernel<<<GRID_MAIN, THREADS>>>(Z, rbf, idx_i, idx_j, W_rbf, b_rbf, W, out,
                                        emb, out0);
}

// round 16
// speedup vs baseline: 1.2721x; 1.0012x over previous
#include <cuda_runtime.h>
#include <cuda_fp16.h>
#include <cstdint>

#define EMB      128
#define NRAD     16
#define N_ATOMS_ 100000
#define N_EDGES_ 1000000
#define N_ELEM   95
#define TILE     128
#define NTILES   ((N_EDGES_ + TILE - 1) / TILE)   // 7813
#define GRID_MAIN 296
#define THREADS  256

// ---------------- smem layout (bytes) ----------------
#define OFF_BT2   0                    // W3^T fp16 frags [ks(8)][ntp(4x2)][q(8)][c(4)]x16B = 32KB
#define OFF_BT1   32768                // W_rbf^T fp16 frags = 4KB
#define OFF_RBFH  36864                // rbf tile fp16 A-frags, x2 buffers = 8KB
#define OFF_BIAS  45056                // b_rbf [128] f32
#define OFF_ZP    45568                // zp pair-index [128] int, x2 buffers = 1KB
#define SMEM_TOTAL 46592

// prep1 fp32 projections; prep2 merged fp16 pair table, PERMUTATION-swizzled:
// physical col n = 64*nh + 16*j + 4*c + 2*nto + b
//   -> pos = p*128 + nh*64 + c*16 + j*4 + nto*2 + b
__device__ float g_EW1f[N_ELEM * EMB];
__device__ float g_EW2f[N_ELEM * EMB];
__device__ __align__(16) __half g_EWPh[N_ELEM * N_ELEM * EMB];   // 2.31MB

// ---------------- helpers ----------------
__device__ __forceinline__ float silu_tanh(float x) {
    float t;
    asm("tanh.approx.f32 %0, %1;" : "=f"(t) : "f"(0.5f * x));
    return 0.5f * x * (1.0f + t);
}
__device__ __forceinline__ uint32_t pack2(float lo, float hi) {
    uint32_t r;
    asm("cvt.rn.f16x2.f32 %0, %1, %2;" : "=r"(r) : "f"(hi), "f"(lo));
    return r;
}
// packed fp16 silu for GEMM1: one MUFU for two lanes.
// hx = 0.5*x; r = hx * (1 + tanh(hx))  == x*sigmoid(x)
__device__ __forceinline__ uint32_t silu2_f16(float lo, float hi) {
    uint32_t x = pack2(lo, hi), hx, t;
    asm("mul.rn.f16x2 %0, %1, %2;" : "=r"(hx) : "r"(x), "r"(0x38003800u));  // {0.5,0.5}
    asm("tanh.approx.f16x2 %0, %1;" : "=r"(t) : "r"(hx));
    asm("add.rn.f16x2 %0, %1, %2;" : "=r"(t) : "r"(t), "r"(0x3C003C00u));   // +{1,1}
    asm("mul.rn.f16x2 %0, %1, %2;" : "=r"(hx) : "r"(hx), "r"(t));
    return hx;
}
__device__ __forceinline__ void mma_f16(float* d,
    uint32_t a0, uint32_t a1, uint32_t a2, uint32_t a3,
    uint32_t b0, uint32_t b1) {
    asm volatile(
        "mma.sync.aligned.m16n8k16.row.col.f32.f16.f16.f32 "
        "{%0,%1,%2,%3}, {%4,%5,%6,%7}, {%8,%9}, {%0,%1,%2,%3};"
        : "+f"(d[0]), "+f"(d[1]), "+f"(d[2]), "+f"(d[3])
        : "r"(a0), "r"(a1), "r"(a2), "r"(a3), "r"(b0), "r"(b1));
}
__device__ __forceinline__ int physmap(int kk) {
    return 4 * ((kk & 7) >> 1) + 2 * (kk >> 3) + (kk & 1);
}

// ---------------- prep1: EW1f = emb@W1 + b, EW2f = emb@W2 (fp32 linear) ----------------
__global__ void prep_kernel(const float* __restrict__ emb, const float* __restrict__ W,
                            const float* __restrict__ b) {
    __shared__ float p1[EMB], p2[EMB];
    int z = blockIdx.x, n = threadIdx.x & 127, h = threadIdx.x >> 7;
    const float* er = emb + z * EMB;
    float s1 = 0.0f, s2 = 0.0f;
    int k0 = h * 64;
#pragma unroll 8
    for (int k = k0; k < k0 + 64; k++) {
        float ev = er[k];
        s1 += ev * W[k * EMB + n];
        s2 += ev * W[(EMB + k) * EMB + n];
    }
    if (h) { p1[n] = s1; p2[n] = s2; }
    __syncthreads();
    if (!h) {
        g_EW1f[z * EMB + n] = s1 + p1[n] + b[n];
        g_EW2f[z * EMB + n] = s2 + p2[n];
    }
}

// ---------------- prep2: EWP (merged pair table), permutation-swizzled ----------------
__global__ void prep2_kernel() {
    int p = blockIdx.x, n = threadIdx.x;
    int zi = p / N_ELEM, zj = p - zi * N_ELEM;
    float v = g_EW1f[zi * EMB + n] + g_EW2f[zj * EMB + n];
    int nh = n >> 6, m = n & 63;
    int j = m >> 4, c4 = (m >> 2) & 3, nto = (m >> 1) & 1, bb = m & 1;
    g_EWPh[(size_t)p * EMB + nh * 64 + c4 * 16 + j * 4 + nto * 2 + bb] = __float2half(v);
}

// ---------------- main fused edge kernel (also does x_0 copy) ----------------
__global__ void __launch_bounds__(THREADS, 2)
main_kernel(const int* __restrict__ Z, const float* __restrict__ rbf,
            const int* __restrict__ idx_i, const int* __restrict__ idx_j,
            const float* __restrict__ W_rbf, const float* __restrict__ b_rbf,
            const float* __restrict__ W, float* __restrict__ out,
            const float* __restrict__ emb, float* __restrict__ out0) {
    __shared__ char smem[SMEM_TOTAL];
    const int tid  = threadIdx.x;
    const int wid  = tid >> 5, lane = tid & 31;
    const int q    = lane >> 2, c = lane & 3;
    const int m0   = (wid & 3) * 32;     // warp's 32 rows (2 m-tiles)
    const int n0   = (wid >> 2) * 64;    // warp's n-half
    const int ntpb = n0 >> 4;            // global ntp base (0 or 4)

    // staging maps
    const int prow = tid >> 1, ph = tid & 1;     // rbf: 2 threads/row
    const int srp  = prow >> 4, sq = prow & 7, shi = (prow >> 3) & 1;

    // ---- x_0 = embeddings[Z] (independent; overlaps smem fills) ----
    for (int i = blockIdx.x * THREADS + tid; i < N_ATOMS_ * (EMB / 4);
         i += GRID_MAIN * THREADS) {
        int a = i >> 5, qq = i & 31;
        ((float4*)out0)[(size_t)a * 32 + qq] = ((const float4*)emb)[(size_t)Z[a] * 32 + qq];
    }

    // ---- one-time fills ----
    for (int idx = tid; idx < EMB * NRAD; idx += THREADS) {
        int n = idx & 127, k = idx >> 7;
        int nt1 = n >> 3, qn = n & 7, p = physmap(k);
        int cc = p >> 2, slot = p & 3, side = nt1 & 1, ntp = nt1 >> 1;
        __half h = __float2half(W_rbf[k * EMB + n]);
        *(unsigned short*)(smem + OFF_BT1 + ntp * 512 + qn * 64 + cc * 16 +
                           side * 8 + slot * 2) = __half_as_ushort(h);
    }
    // BT2: W3^T with N-PERMUTATION: physical col n -> logical tile g, in-tile qB
    for (int idx = tid; idx < EMB * EMB; idx += THREADS) {
        int n = idx & 127, k = idx >> 7;
        int ks = k >> 4, kk = k & 15, p = physmap(kk);
        int cc = p >> 2, slot = p & 3;
        int nh = n >> 6, m = n & 63;
        int j = m >> 4, c4 = (m >> 2) & 3, nto = (m >> 1) & 1, bb = m & 1;
        int g  = nh * 8 + 2 * j + nto;      // global logical n8-tile
        int qB = 2 * c4 + bb;               // in-tile n index
        __half h = __float2half(W[(2 * EMB + k) * EMB + n]);   // W3[k][n]
        *(unsigned short*)(smem + OFF_BT2 + ks * 4096 + (g >> 1) * 512 + qB * 64 +
                           cc * 16 + (g & 1) * 8 + slot * 2) = __half_as_ushort(h);
    }
    if (tid < EMB) ((float*)(smem + OFF_BIAS))[tid] = b_rbf[tid];

    // ---- prologue: stage first tile into buffer 0 ----
    int t = blockIdx.x;
    {
        long eb = (long)t * TILE;
        long e  = eb + prow; if (e >= N_EDGES_) e = N_EDGES_ - 1;
        float4 a = ((const float4*)rbf)[e * 4 + ph];
        float4 b = ((const float4*)rbf)[e * 4 + ph + 2];
        char* rbb = smem + OFF_RBFH + srp * 512 + sq * 64 + shi * 8;
        *(uint2*)(rbb + (2 * ph) * 16)     = make_uint2(pack2(a.x, a.y), pack2(b.x, b.y));
        *(uint2*)(rbb + (2 * ph + 1) * 16) = make_uint2(pack2(a.z, a.w), pack2(b.z, b.w));
        if (tid < TILE) {
            long ez = eb + tid; if (ez >= N_EDGES_) ez = N_EDGES_ - 1;
            ((int*)(smem + OFF_ZP))[tid] = Z[idx_i[ez]] * N_ELEM + Z[idx_j[ez]];
        }
    }
    __syncthreads();

    int buf = 0;
    for (; t < NTILES; t += GRID_MAIN) {
        // ---- prefetch next tile's staging data ----
        float4 pa, pb; int pzp = 0;
        {
            int tn = t + GRID_MAIN;
            long eb = (long)(tn < NTILES ? tn : t) * TILE;
            long e  = eb + prow; if (e >= N_EDGES_) e = N_EDGES_ - 1;
            pa = ((const float4*)rbf)[e * 4 + ph];
            pb = ((const float4*)rbf)[e * 4 + ph + 2];
            if (tid < TILE) {
                long ez = eb + tid; if (ez >= N_EDGES_) ez = N_EDGES_ - 1;
                pzp = Z[idx_i[ez]] * N_ELEM + Z[idx_j[ez]];
            }
        }

        const long base = (long)t * TILE;
        const char* rb  = smem + OFF_RBFH + buf * 4096;
        const int* zp_s = (const int*)(smem + OFF_ZP + buf * 512);

        // ---- A operands for GEMM1: one LDS.128 per m-tile ----
        uint4 ar[2];
#pragma unroll
        for (int mt = 0; mt < 2; mt++)
            ar[mt] = *(const uint4*)(rb + (m0 / 16 + mt) * 512 + q * 64 + c * 16);

        // ---- fused GEMM1 -> silu(f16x2) -> GEMM2, one k-step at a time ----
        float dacc[2][8][4];
#pragma unroll
        for (int mt = 0; mt < 2; mt++)
#pragma unroll
            for (int nt = 0; nt < 8; nt++)
#pragma unroll
                for (int r = 0; r < 4; r++) dacc[mt][nt][r] = 0.0f;

        const float* bias_s = (const float*)(smem + OFF_BIAS);
#pragma unroll
        for (int ks = 0; ks < 8; ks++) {
            uint4 b1v = *(const uint4*)(smem + OFF_BT1 + ks * 512 + q * 64 + c * 16);
            float2 bb0 = *(const float2*)(bias_s + 16 * ks + 2 * c);
            float2 bb1 = *(const float2*)(bias_s + 16 * ks + 8 + 2 * c);
            uint32_t afrag[2][4];
#pragma unroll
            for (int mt = 0; mt < 2; mt++) {
                float d0[4] = {bb0.x, bb0.y, bb0.x, bb0.y};
                mma_f16(d0, ar[mt].x, ar[mt].z, ar[mt].y, ar[mt].w, b1v.x, b1v.y);
                afrag[mt][0] = silu2_f16(d0[0], d0[1]);
                afrag[mt][1] = silu2_f16(d0[2], d0[3]);
                float d1[4] = {bb1.x, bb1.y, bb1.x, bb1.y};
                mma_f16(d1, ar[mt].x, ar[mt].z, ar[mt].y, ar[mt].w, b1v.z, b1v.w);
                afrag[mt][2] = silu2_f16(d1[0], d1[1]);
                afrag[mt][3] = silu2_f16(d1[2], d1[3]);
            }
#pragma unroll
            for (int ntp = 0; ntp < 4; ntp++) {
                uint4 bv = *(const uint4*)(smem + OFF_BT2 + ks * 4096 +
                                           (ntpb + ntp) * 512 + q * 64 + c * 16);
                mma_f16(dacc[0][2 * ntp],     afrag[0][0], afrag[0][1], afrag[0][2],
                        afrag[0][3], bv.x, bv.y);
                mma_f16(dacc[1][2 * ntp],     afrag[1][0], afrag[1][1], afrag[1][2],
                        afrag[1][3], bv.x, bv.y);
                mma_f16(dacc[0][2 * ntp + 1], afrag[0][0], afrag[0][1], afrag[0][2],
                        afrag[0][3], bv.z, bv.w);
                mma_f16(dacc[1][2 * ntp + 1], afrag[1][0], afrag[1][1], afrag[1][2],
                        afrag[1][3], bv.z, bv.w);
            }
        }

        // ---- epilogue: permuted cols -> STG.128; EWP gather 2x LDG.128 ----
#pragma unroll
        for (int mt = 0; mt < 2; mt++) {
#pragma unroll
            for (int sub = 0; sub < 2; sub++) {
                int r = m0 + 16 * mt + 8 * sub + q;
                long e = base + r;
                if (e < N_EDGES_) {
                    int zp = zp_s[r];
                    const __half* hp = g_EWPh + (size_t)zp * EMB + n0 + c * 16;
                    uint4 u0 = *(const uint4*)(hp);
                    uint4 u1 = *(const uint4*)(hp + 8);
                    float* op = out + (size_t)e * EMB + n0 + 4 * c;
                    uint32_t uh[8] = {u0.x, u0.y, u0.z, u0.w, u1.x, u1.y, u1.z, u1.w};
#pragma unroll
                    for (int j = 0; j < 4; j++) {
                        float2 fa = __half22float2(*(const __half2*)&uh[2 * j]);
                        float2 fb = __half22float2(*(const __half2*)&uh[2 * j + 1]);
                        float4 o;
                        o.x = silu_tanh(dacc[mt][2 * j][2 * sub + 0] + fa.x);
                        o.y = silu_tanh(dacc[mt][2 * j][2 * sub + 1] + fa.y);
                        o.z = silu_tanh(dacc[mt][2 * j + 1][2 * sub + 0] + fb.x);
                        o.w = silu_tanh(dacc[mt][2 * j + 1][2 * sub + 1] + fb.y);
                        *(float4*)(op + 16 * j) = o;
                    }
                }
            }
        }

        // ---- store prefetched staging data into the other buffer ----
        {
            int nb = buf ^ 1;
            char* rbb = smem + OFF_RBFH + nb * 4096 + srp * 512 + sq * 64 + shi * 8;
            *(uint2*)(rbb + (2 * ph) * 16)     = make_uint2(pack2(pa.x, pa.y), pack2(pb.x, pb.y));
            *(uint2*)(rbb + (2 * ph + 1) * 16) = make_uint2(pack2(pa.z, pa.w), pack2(pb.z, pb.w));
            if (tid < TILE) ((int*)(smem + OFF_ZP + nb * 512))[tid] = pzp;
        }
        __syncthreads();
        buf ^= 1;
    }
}

// ---------------- launch ----------------
extern "C" void kernel_launch(void* const* d_in, const int* in_sizes, int n_in,
                              void* d_out, int out_size) {
    (void)in_sizes; (void)n_in; (void)out_size;
    const int*   Z     = (const int*)d_in[0];
    const float* rbf   = (const float*)d_in[1];
    const int*   idx_i = (const int*)d_in[2];
    const int*   idx_j = (const int*)d_in[3];
    const float* emb   = (const float*)d_in[4];
    const float* W_rbf = (const float*)d_in[5];
    const float* b_rbf = (const float*)d_in[6];
    const float* W     = (const float*)d_in[7];
    const float* b     = (const float*)d_in[8];
    float* out  = (float*)d_out;
    float* out0 = out + (size_t)N_EDGES_ * EMB;

    prep_kernel<<<N_ELEM, 256>>>(emb, W, b);
    prep2_kernel<<<N_ELEM * N_ELEM, EMB>>>();
    main_kernel<<<GRID_MAIN, THREADS>>>(Z, rbf, idx_i, idx_j, W_rbf, b_rbf, W, out,
                                        emb, out0);
}